// round 9
// baseline (speedup 1.0000x reference)
#include <cuda_runtime.h>
#include <cuda_bf16.h>

// KL(p||q) for diagonal Gaussians, mean over batch.
// Primary: Round-1 main loop (best measured codegen ~6.5 TB/s), each block
// publishes partial + release-flag. Finish kernel: PDL-launched (resident
// during primary), consumes partials AS THEY ARRIVE by spinning on per-block
// flags in FIXED order (deterministic sum), resets flags for graph replay.

#define NBLOCKS 1024
#define NTHREADS 256
#define FIN_THREADS 256
#define PER_THREAD (NBLOCKS / FIN_THREADS)   // 4

__device__ float g_partials[NBLOCKS];
__device__ unsigned int g_flags[NBLOCKS];    // zero-initialized once

__global__ __launch_bounds__(NTHREADS) void kl_partial_kernel(
    const float* __restrict__ p_mu,
    const float* __restrict__ p_lv,
    const float* __restrict__ q_mu,
    const float* __restrict__ q_lv,
    int n4)
{
    // Release the dependent finish kernel immediately; it spins on flags.
    cudaTriggerProgrammaticLaunchCompletion();

    const float4* pm4 = reinterpret_cast<const float4*>(p_mu);
    const float4* pl4 = reinterpret_cast<const float4*>(p_lv);
    const float4* qm4 = reinterpret_cast<const float4*>(q_mu);
    const float4* ql4 = reinterpret_cast<const float4*>(q_lv);

    float acc = 0.0f;
    int stride = gridDim.x * blockDim.x;
    for (int i = blockIdx.x * blockDim.x + threadIdx.x; i < n4; i += stride) {
        float4 a = pm4[i];
        float4 b = pl4[i];
        float4 c = qm4[i];
        float4 d = ql4[i];

        {
            float lr = d.x - b.x;
            float dm = a.x - c.x;
            acc += lr + __expf(-lr) + dm * dm * __expf(-d.x) - 1.0f;
        }
        {
            float lr = d.y - b.y;
            float dm = a.y - c.y;
            acc += lr + __expf(-lr) + dm * dm * __expf(-d.y) - 1.0f;
        }
        {
            float lr = d.z - b.z;
            float dm = a.z - c.z;
            acc += lr + __expf(-lr) + dm * dm * __expf(-d.z) - 1.0f;
        }
        {
            float lr = d.w - b.w;
            float dm = a.w - c.w;
            acc += lr + __expf(-lr) + dm * dm * __expf(-d.w) - 1.0f;
        }
    }

    // Block reduce
    #pragma unroll
    for (int off = 16; off > 0; off >>= 1)
        acc += __shfl_down_sync(0xFFFFFFFFu, acc, off);

    __shared__ float smem[NTHREADS / 32];
    int lane = threadIdx.x & 31;
    int warp = threadIdx.x >> 5;
    if (lane == 0) smem[warp] = acc;
    __syncthreads();

    if (warp == 0) {
        acc = (lane < NTHREADS / 32) ? smem[lane] : 0.0f;
        #pragma unroll
        for (int off = 4; off > 0; off >>= 1)
            acc += __shfl_down_sync(0xFFFFFFFFu, acc, off);
        if (lane == 0) {
            g_partials[blockIdx.x] = acc;
            __threadfence();                         // partial visible before flag
            *(volatile unsigned int*)&g_flags[blockIdx.x] = 1u;  // release
        }
    }
}

__global__ __launch_bounds__(FIN_THREADS) void kl_finish_kernel(float* out, float scale)
{
    // PDL-resident: consume partials as they arrive, in fixed index order.
    const int tid = threadIdx.x;
    volatile unsigned int* vf = (volatile unsigned int*)g_flags;
    volatile float*        vp = (volatile float*)g_partials;

    float acc = 0.0f;
    #pragma unroll
    for (int k = 0; k < PER_THREAD; ++k) {
        int j = tid + k * FIN_THREADS;
        while (vf[j] == 0u) { }       // spin until block j published
        acc += vp[j];                  // fixed-order accumulation
        vf[j] = 0u;                    // reset for next graph replay
    }

    #pragma unroll
    for (int off = 16; off > 0; off >>= 1)
        acc += __shfl_down_sync(0xFFFFFFFFu, acc, off);

    __shared__ float smem[FIN_THREADS / 32];
    int lane = tid & 31;
    int warp = tid >> 5;
    if (lane == 0) smem[warp] = acc;
    __syncthreads();

    if (warp == 0) {
        acc = (lane < FIN_THREADS / 32) ? smem[lane] : 0.0f;
        #pragma unroll
        for (int off = 4; off > 0; off >>= 1)
            acc += __shfl_down_sync(0xFFFFFFFFu, acc, off);
        if (lane == 0) out[0] = acc * scale;
    }
}

extern "C" void kernel_launch(void* const* d_in, const int* in_sizes, int n_in,
                              void* d_out, int out_size)
{
    const float* p_mu = (const float*)d_in[0];
    const float* p_lv = (const float*)d_in[1];
    const float* q_mu = (const float*)d_in[2];
    const float* q_lv = (const float*)d_in[3];
    float* out = (float*)d_out;

    int n  = in_sizes[0];     // B*D
    int n4 = n >> 2;
    int B  = n / 512;         // D = 512
    float scale = 0.5f / (float)B;

    kl_partial_kernel<<<NBLOCKS, NTHREADS>>>(p_mu, p_lv, q_mu, q_lv, n4);

    // PDL finish: launches once all primary blocks have triggered; overlaps
    // its reduction with the primary's execution via flag spinning.
    cudaLaunchConfig_t cfg = {};
    cfg.gridDim  = dim3(1, 1, 1);
    cfg.blockDim = dim3(FIN_THREADS, 1, 1);
    cfg.dynamicSmemBytes = 0;
    cfg.stream = 0;
    cudaLaunchAttribute attrs[1];
    attrs[0].id = cudaLaunchAttributeProgrammaticStreamSerialization;
    attrs[0].val.programmaticStreamSerializationAllowed = 1;
    cfg.attrs = attrs;
    cfg.numAttrs = 1;
    cudaLaunchKernelEx(&cfg, kl_finish_kernel, out, scale);
}

// round 10
// speedup vs baseline: 1.1225x; 1.1225x over previous
#include <cuda_runtime.h>
#include <cuda_bf16.h>

// KL(p||q) for diagonal Gaussians, mean over batch.
// R8 structure (best measured: R1 main loop + PDL finish) with one change:
// NBLOCKS = 1184 = 148 SMs x 8 CTAs -> perfect per-SM CTA balance (1024
// blocks left 12 SMs underloaded). Loop body/codegen unchanged.
// Deterministic: fixed grid, fixed reduction order.

#define NBLOCKS 1184
#define NTHREADS 256
#define FIN_THREADS 1024

__device__ float g_partials[NBLOCKS];

__global__ __launch_bounds__(NTHREADS) void kl_partial_kernel(
    const float* __restrict__ p_mu,
    const float* __restrict__ p_lv,
    const float* __restrict__ q_mu,
    const float* __restrict__ q_lv,
    int n4)
{
    // Release the dependent finish kernel; it sleeps in gridDepSync.
    cudaTriggerProgrammaticLaunchCompletion();

    const float4* pm4 = reinterpret_cast<const float4*>(p_mu);
    const float4* pl4 = reinterpret_cast<const float4*>(p_lv);
    const float4* qm4 = reinterpret_cast<const float4*>(q_mu);
    const float4* ql4 = reinterpret_cast<const float4*>(q_lv);

    float acc = 0.0f;
    int stride = gridDim.x * blockDim.x;
    for (int i = blockIdx.x * blockDim.x + threadIdx.x; i < n4; i += stride) {
        float4 a = pm4[i];
        float4 b = pl4[i];
        float4 c = qm4[i];
        float4 d = ql4[i];

        {
            float lr = d.x - b.x;
            float dm = a.x - c.x;
            acc += lr + __expf(-lr) + dm * dm * __expf(-d.x) - 1.0f;
        }
        {
            float lr = d.y - b.y;
            float dm = a.y - c.y;
            acc += lr + __expf(-lr) + dm * dm * __expf(-d.y) - 1.0f;
        }
        {
            float lr = d.z - b.z;
            float dm = a.z - c.z;
            acc += lr + __expf(-lr) + dm * dm * __expf(-d.z) - 1.0f;
        }
        {
            float lr = d.w - b.w;
            float dm = a.w - c.w;
            acc += lr + __expf(-lr) + dm * dm * __expf(-d.w) - 1.0f;
        }
    }

    // Block reduce
    #pragma unroll
    for (int off = 16; off > 0; off >>= 1)
        acc += __shfl_down_sync(0xFFFFFFFFu, acc, off);

    __shared__ float smem[NTHREADS / 32];
    int lane = threadIdx.x & 31;
    int warp = threadIdx.x >> 5;
    if (lane == 0) smem[warp] = acc;
    __syncthreads();

    if (warp == 0) {
        acc = (lane < NTHREADS / 32) ? smem[lane] : 0.0f;
        #pragma unroll
        for (int off = 4; off > 0; off >>= 1)
            acc += __shfl_down_sync(0xFFFFFFFFu, acc, off);
        if (lane == 0) g_partials[blockIdx.x] = acc;
    }
}

__global__ __launch_bounds__(FIN_THREADS) void kl_finish_kernel(float* out, float scale)
{
    // PDL: launched early, sleeps here until the primary grid fully retires
    // (memory visibility guaranteed by PDL semantics).
    cudaGridDependencySynchronize();

    const int tid = threadIdx.x;
    float acc = 0.0f;
    for (int j = tid; j < NBLOCKS; j += FIN_THREADS)   // 1-2 loads, fixed order
        acc += g_partials[j];

    #pragma unroll
    for (int off = 16; off > 0; off >>= 1)
        acc += __shfl_down_sync(0xFFFFFFFFu, acc, off);

    __shared__ float smem[FIN_THREADS / 32];
    int lane = tid & 31;
    int warp = tid >> 5;
    if (lane == 0) smem[warp] = acc;
    __syncthreads();

    if (warp == 0) {
        acc = smem[lane];
        #pragma unroll
        for (int off = 16; off > 0; off >>= 1)
            acc += __shfl_down_sync(0xFFFFFFFFu, acc, off);
        if (lane == 0) out[0] = acc * scale;
    }
}

extern "C" void kernel_launch(void* const* d_in, const int* in_sizes, int n_in,
                              void* d_out, int out_size)
{
    const float* p_mu = (const float*)d_in[0];
    const float* p_lv = (const float*)d_in[1];
    const float* q_mu = (const float*)d_in[2];
    const float* q_lv = (const float*)d_in[3];
    float* out = (float*)d_out;

    int n  = in_sizes[0];     // B*D
    int n4 = n >> 2;
    int B  = n / 512;         // D = 512
    float scale = 0.5f / (float)B;

    kl_partial_kernel<<<NBLOCKS, NTHREADS>>>(p_mu, p_lv, q_mu, q_lv, n4);

    // PDL finish: launch latency overlaps the primary kernel's execution.
    cudaLaunchConfig_t cfg = {};
    cfg.gridDim  = dim3(1, 1, 1);
    cfg.blockDim = dim3(FIN_THREADS, 1, 1);
    cfg.dynamicSmemBytes = 0;
    cfg.stream = 0;
    cudaLaunchAttribute attrs[1];
    attrs[0].id = cudaLaunchAttributeProgrammaticStreamSerialization;
    attrs[0].val.programmaticStreamSerializationAllowed = 1;
    cfg.attrs = attrs;
    cfg.numAttrs = 1;
    cudaLaunchKernelEx(&cfg, kl_finish_kernel, out, scale);
}

// round 11
// speedup vs baseline: 1.1965x; 1.0659x over previous
#include <cuda_runtime.h>
#include <cuda_bf16.h>

// KL(p||q) for diagonal Gaussians, mean over batch. SINGLE kernel.
// R1 main loop (best measured codegen, 1024x256, 8 exact iters/thread).
// Tail: each block converts its non-negative fp32 partial to fixed-point
// (x 2^20) and does ONE packed u64 atomicAdd: sum in bits[0:50), block
// count in bits[50:62). Integer adds commute -> deterministic total.
// The block that observes count==1023 in the returned value is last:
// writes out[0] and resets the accumulator for graph replay.

#define NBLOCKS 1024
#define NTHREADS 256
#define COUNT_SHIFT 50
#define SUM_MASK ((1ULL << COUNT_SHIFT) - 1ULL)
#define FIXED_SCALE 1048576.0   // 2^20

__device__ unsigned long long g_acc = 0ULL;

__global__ __launch_bounds__(NTHREADS) void kl_onepass_kernel(
    const float* __restrict__ p_mu,
    const float* __restrict__ p_lv,
    const float* __restrict__ q_mu,
    const float* __restrict__ q_lv,
    float* __restrict__ out,
    int n4, float scale)
{
    const float4* pm4 = reinterpret_cast<const float4*>(p_mu);
    const float4* pl4 = reinterpret_cast<const float4*>(p_lv);
    const float4* qm4 = reinterpret_cast<const float4*>(q_mu);
    const float4* ql4 = reinterpret_cast<const float4*>(q_lv);

    float acc = 0.0f;
    int stride = gridDim.x * blockDim.x;
    for (int i = blockIdx.x * blockDim.x + threadIdx.x; i < n4; i += stride) {
        float4 a = pm4[i];
        float4 b = pl4[i];
        float4 c = qm4[i];
        float4 d = ql4[i];

        {
            float lr = d.x - b.x;
            float dm = a.x - c.x;
            acc += lr + __expf(-lr) + dm * dm * __expf(-d.x) - 1.0f;
        }
        {
            float lr = d.y - b.y;
            float dm = a.y - c.y;
            acc += lr + __expf(-lr) + dm * dm * __expf(-d.y) - 1.0f;
        }
        {
            float lr = d.z - b.z;
            float dm = a.z - c.z;
            acc += lr + __expf(-lr) + dm * dm * __expf(-d.z) - 1.0f;
        }
        {
            float lr = d.w - b.w;
            float dm = a.w - c.w;
            acc += lr + __expf(-lr) + dm * dm * __expf(-d.w) - 1.0f;
        }
    }

    // Block reduce
    #pragma unroll
    for (int off = 16; off > 0; off >>= 1)
        acc += __shfl_down_sync(0xFFFFFFFFu, acc, off);

    __shared__ float smem[NTHREADS / 32];
    int lane = threadIdx.x & 31;
    int warp = threadIdx.x >> 5;
    if (lane == 0) smem[warp] = acc;
    __syncthreads();

    if (warp == 0) {
        acc = (lane < NTHREADS / 32) ? smem[lane] : 0.0f;
        #pragma unroll
        for (int off = 4; off > 0; off >>= 1)
            acc += __shfl_down_sync(0xFFFFFFFFu, acc, off);

        if (lane == 0) {
            // Non-negative fixed-point contribution + count in high bits.
            unsigned long long mine =
                (unsigned long long)__double2ll_rn((double)acc * FIXED_SCALE)
                + (1ULL << COUNT_SHIFT);
            unsigned long long old = atomicAdd(&g_acc, mine);
            unsigned long long cnt = old >> COUNT_SHIFT;
            if (cnt == (unsigned long long)(NBLOCKS - 1)) {
                // I'm the last block: total = old + mine (deterministic).
                unsigned long long total = (old + mine) & SUM_MASK;
                out[0] = (float)((double)total * (1.0 / FIXED_SCALE) * (double)scale);
                g_acc = 0ULL;          // reset for next graph replay
                __threadfence();
            }
        }
    }
}

extern "C" void kernel_launch(void* const* d_in, const int* in_sizes, int n_in,
                              void* d_out, int out_size)
{
    const float* p_mu = (const float*)d_in[0];
    const float* p_lv = (const float*)d_in[1];
    const float* q_mu = (const float*)d_in[2];
    const float* q_lv = (const float*)d_in[3];
    float* out = (float*)d_out;

    int n  = in_sizes[0];     // B*D
    int n4 = n >> 2;
    int B  = n / 512;         // D = 512
    float scale = 0.5f / (float)B;

    kl_onepass_kernel<<<NBLOCKS, NTHREADS>>>(p_mu, p_lv, q_mu, q_lv, out, n4, scale);
}